// round 8
// baseline (speedup 1.0000x reference)
#include <cuda_runtime.h>
#include <math.h>
#include <stdint.h>

// EnhancedFinancialGAT collapse: initial node features are uniform over nodes,
// so GAT attention (softmax weights summing to 1 per dst) aggregates identical
// messages -> each GAT layer == relu(W @ g + b). Whole net = per-item MLP.
//
// R6 -> R7: single cp.async.bulk stream drains at ~30B/cyc/SM (measured
// ~2us/64KB tile) -> transfer-rate bound. Switch weight streaming to
// multi-warp cp.async.cg (LDGSTS, 16B/thread chunks) with commit/wait_group.

#define IN_DIM 64
#define NT 27
#define S  3
#define SLOT_FLOATS 16384          // 64KB slot
#define SLOT_BYTES  (SLOT_FLOATS * 4)
#define ACT_STRIDE 704             // per item: s0[320] s1[256] s2[128]

struct Tile {
    uint8_t  wi;    // weight/bias index
    uint8_t  c4;    // float4 per row
    uint8_t  vin;   // 0:+0(s0) 1:+320(s1) 2:+128(s0 hi)
    uint8_t  vout;  // 0:+0     1:+320     2:+576(s2)
    uint16_t row0;
    uint16_t rows;
    uint16_t voff;
};

__device__ __constant__ Tile g_tiles[NT] = {
    {0, 16, 0, 1, 0, 256, 0},                                     // W_in
    {1, 64, 1, 0,   0, 64,   0}, {1, 64, 1, 0,  64, 64,  64},     // gat0
    {1, 64, 1, 0, 128, 64, 128}, {1, 64, 1, 0, 192, 64, 192},
    {2, 64, 0, 1,   0, 64,   0}, {2, 64, 0, 1,  64, 64,  64},     // gat1
    {2, 64, 0, 1, 128, 64, 128}, {2, 64, 0, 1, 192, 64, 192},
    {3, 64, 1, 0,   0, 64,   0}, {3, 64, 1, 0,  64, 64,  64},     // gat2
    {3, 64, 1, 0, 128, 64, 128}, {3, 64, 1, 0, 192, 64, 192},
    {4, 80, 0, 1,   0, 32,   0}, {4, 80, 0, 1,  32, 32,  32},     // fuse
    {4, 80, 0, 1,  64, 32,  64}, {4, 80, 0, 1,  96, 32,  96},
    {4, 80, 0, 1, 128, 32, 128}, {4, 80, 0, 1, 160, 32, 160},
    {4, 80, 0, 1, 192, 32, 192}, {4, 80, 0, 1, 224, 32, 224},
    {5, 64, 1, 0,   0, 64,   0}, {5, 64, 1, 0,  64, 64,  64},     // p1
    {6, 64, 1, 0,   0, 64, 128}, {6, 64, 1, 0,  64, 64, 192},     // d1
    {7, 32, 0, 2,   0, 64,   0},                                  // p2
    {8, 32, 2, 2,   0, 64,  64},                                  // d2
};

__device__ __forceinline__ uint32_t smem_u32(const void* p) {
    uint32_t a;
    asm("{ .reg .u64 t; cvta.to.shared.u64 t, %1; cvt.u32.u64 %0, t; }"
        : "=r"(a) : "l"(p));
    return a;
}
__device__ __forceinline__ void cp16(uint32_t dst, const void* src) {
    asm volatile("cp.async.cg.shared.global [%0], [%1], 16;"
                 :: "r"(dst), "l"(src) : "memory");
}
__device__ __forceinline__ void cp_commit() {
    asm volatile("cp.async.commit_group;" ::: "memory");
}
template<int N>
__device__ __forceinline__ void cp_wait() {
    asm volatile("cp.async.wait_group %0;" :: "n"(N) : "memory");
}

extern __shared__ __align__(16) float smem_dyn[];

__global__ __launch_bounds__(1024)
void gat_ldgsts_kernel(
    const float* __restrict__ x, const int* __restrict__ company_idx,
    const float* __restrict__ W_in,  const float* __restrict__ b_in,
    const float* __restrict__ gat_W, const float* __restrict__ gat_b,
    const float* __restrict__ emb,
    const float* __restrict__ W_fuse, const float* __restrict__ b_fuse,
    const float* __restrict__ W_p1, const float* __restrict__ b_p1,
    const float* __restrict__ W_p2, const float* __restrict__ b_p2,
    const float* __restrict__ W_p3, const float* __restrict__ b_p3,
    const float* __restrict__ W_d1, const float* __restrict__ b_d1,
    const float* __restrict__ W_d2, const float* __restrict__ b_d2,
    const float* __restrict__ W_d3, const float* __restrict__ b_d3,
    float* __restrict__ out)
{
    float* act = smem_dyn + S * SLOT_FLOATS;   // 2 * ACT_STRIDE floats

    const int tid = threadIdx.x;
    const int b0  = blockIdx.x * 2;

    const float* wp[9] = {W_in, gat_W, gat_W + 65536, gat_W + 131072,
                          W_fuse, W_p1, W_d1, W_p2, W_d2};
    const float* bp[9] = {b_in, gat_b, gat_b + 256, gat_b + 512,
                          b_fuse, b_p1, b_d1, b_p2, b_d2};

    const uint32_t slot_a = smem_u32(smem_dyn);

    // initial activations: x rows + emb rows for both items
    if (tid < 128) {
        const int it = tid >> 6, c = tid & 63;
        const int bb = b0 + it;
        float* s0 = act + it * ACT_STRIDE;
        s0[c]       = __ldg(&x[bb * IN_DIM + c]);
        s0[256 + c] = __ldg(&emb[__ldg(&company_idx[bb]) * IN_DIM + c]);
    }

    // prologue: issue tiles 0 .. S-2 as groups 0 .. S-2
#pragma unroll
    for (int t = 0; t < S - 1; t++) {
        Tile ti = g_tiles[t];
        const int nch = (int)ti.rows * ti.c4;
        const float* src = wp[ti.wi] + (uint32_t)ti.row0 * ti.c4 * 4;
        const uint32_t dst = slot_a + (t % S) * SLOT_BYTES;
        for (int c = tid; c < nch; c += 1024)
            cp16(dst + c * 16, src + c * 4);
        cp_commit();
    }
    __syncthreads();   // also covers act init

    const uint16_t vin_off[3]  = {0, 320, 128};
    const uint16_t vout_off[3] = {0, 320, 576};

    for (int t = 0; t < NT; t++) {
        // issue tile t+S-1 into slot freed by tile t-1 (sealed by last bar)
        const int tn = t + S - 1;
        if (tn < NT) {
            Tile ti = g_tiles[tn];
            const int nch = (int)ti.rows * ti.c4;
            const float* src = wp[ti.wi] + (uint32_t)ti.row0 * ti.c4 * 4;
            const uint32_t dst = slot_a + (tn % S) * SLOT_BYTES;
            for (int c = tid; c < nch; c += 1024)
                cp16(dst + c * 16, src + c * 4);
        }
        cp_commit();   // keep group numbering uniform across threads

        // wait for group t (own copies), then barrier (everyone's copies)
        if      (t < NT - 2) cp_wait<2>();
        else if (t == NT - 2) cp_wait<1>();
        else                  cp_wait<0>();
        __syncthreads();

        const Tile ti = g_tiles[t];
        const int rows = ti.rows;
        const int L    = 1024 / rows;          // 4 / 16 / 32
        const int row  = tid / L;
        const int l    = tid - row * L;
        const int c4   = ti.c4;

        const float4* __restrict__ w4 =
            reinterpret_cast<const float4*>(smem_dyn + (t % S) * SLOT_FLOATS) + row * c4;
        const float4* __restrict__ va =
            reinterpret_cast<const float4*>(act + vin_off[ti.vin]);
        const float4* __restrict__ vb =
            reinterpret_cast<const float4*>(act + ACT_STRIDE + vin_off[ti.vin]);

        float p0 = 0.f, p1a = 0.f, p2a = 0.f, p3a = 0.f;
        float q0 = 0.f, q1a = 0.f, q2a = 0.f, q3a = 0.f;
        for (int i = l; i < c4; i += L) {
            float4 w = w4[i];
            float4 u = va[i];
            float4 v = vb[i];
            p0  = fmaf(w.x, u.x, p0);
            p1a = fmaf(w.y, u.y, p1a);
            p2a = fmaf(w.z, u.z, p2a);
            p3a = fmaf(w.w, u.w, p3a);
            q0  = fmaf(w.x, v.x, q0);
            q1a = fmaf(w.y, v.y, q1a);
            q2a = fmaf(w.z, v.z, q2a);
            q3a = fmaf(w.w, v.w, q3a);
        }
        float rp = (p0 + p1a) + (p2a + p3a);
        float rq = (q0 + q1a) + (q2a + q3a);
        for (int o = L >> 1; o; o >>= 1) {
            rp += __shfl_xor_sync(0xffffffffu, rp, o);
            rq += __shfl_xor_sync(0xffffffffu, rq, o);
        }
        if (l == 0) {
            float bias = __ldg(bp[ti.wi] + ti.row0 + row);
            const int oo = vout_off[ti.vout] + ti.voff + row;
            act[oo]              = fmaxf(rp + bias, 0.f);
            act[ACT_STRIDE + oo] = fmaxf(rq + bias, 0.f);
        }
        __syncthreads();   // seal slot t%S for reuse at iteration t+1
    }

    // heads: warp w -> (item = w>>1, head = w&1)
    const int w = tid >> 5, lane = tid & 31;
    if (w < 4) {
        const int it = w >> 1, head = w & 1;
        const float* s2 = act + it * ACT_STRIDE + 576 + head * 64;
        const float* W  = head ? W_d3 : W_p3;
        float2 wv = __ldg(&reinterpret_cast<const float2*>(W)[lane]);
        float2 vv = reinterpret_cast<const float2*>(s2)[lane];
        float r = fmaf(wv.x, vv.x, wv.y * vv.y);
#pragma unroll
        for (int o = 16; o; o >>= 1) r += __shfl_xor_sync(0xffffffffu, r, o);
        if (lane == 0) {
            const int bb = b0 + it;
            if (head == 0) out[bb] = r + __ldg(b_p3);
            else           out[64 + bb] = 1.f / (1.f + expf(-(r + __ldg(b_d3))));
        }
    }
}

extern "C" void kernel_launch(void* const* d_in, const int* in_sizes, int n_in,
                              void* d_out, int out_size) {
    const float* x      = (const float*)d_in[0];
    const int*   ci     = (const int*)  d_in[1];
    const float* W_in   = (const float*)d_in[4];
    const float* b_in   = (const float*)d_in[5];
    const float* gat_W  = (const float*)d_in[6];
    const float* gat_b  = (const float*)d_in[11];
    const float* emb    = (const float*)d_in[12];
    const float* W_fuse = (const float*)d_in[13];
    const float* b_fuse = (const float*)d_in[14];
    const float* W_p1   = (const float*)d_in[15];
    const float* b_p1   = (const float*)d_in[16];
    const float* W_p2   = (const float*)d_in[17];
    const float* b_p2   = (const float*)d_in[18];
    const float* W_p3   = (const float*)d_in[19];
    const float* b_p3   = (const float*)d_in[20];
    const float* W_d1   = (const float*)d_in[21];
    const float* b_d1   = (const float*)d_in[22];
    const float* W_d2   = (const float*)d_in[23];
    const float* b_d2   = (const float*)d_in[24];
    const float* W_d3   = (const float*)d_in[25];
    const float* b_d3   = (const float*)d_in[26];

    const int B = in_sizes[0] / IN_DIM;  // 64

    const int smem_bytes = S * SLOT_BYTES + 2 * ACT_STRIDE * 4 + 16;
    cudaFuncSetAttribute(gat_ldgsts_kernel,
                         cudaFuncAttributeMaxDynamicSharedMemorySize, smem_bytes);

    gat_ldgsts_kernel<<<B / 2, 1024, smem_bytes>>>(
        x, ci, W_in, b_in, gat_W, gat_b, emb, W_fuse, b_fuse,
        W_p1, b_p1, W_p2, b_p2, W_p3, b_p3,
        W_d1, b_d1, W_d2, b_d2, W_d3, b_d3,
        (float*)d_out);
}

// round 9
// speedup vs baseline: 2.4047x; 2.4047x over previous
#include <cuda_runtime.h>
#include <math.h>
#include <stdint.h>

// EnhancedFinancialGAT collapse: initial node features are uniform over nodes,
// so GAT attention (softmax weights summing to 1 per dst) aggregates identical
// messages -> each GAT layer == relu(W @ g + b). Whole net = per-item MLP.
//
// R8 -> R9: smem-staged pipelines cost ~2us/tile in fixed overhead (R5/R6/R8
// all ~constant per-tile). Drop staging entirely: weights stream L2->registers
// via coalesced LDG.128 (8 lanes per output row = 128B contiguous per row,
// 4-deep load batches, 32 warps -> SM-level MLP >> 100). Only 9 layer barriers.
// 2 items per block (grid 32): each weight fetched once, used for both items.

#define IN_DIM 64
#define ACT_STRIDE 704   // per item: s0[320] | s1[256] | s2[128]

// One dense layer: out[r] = relu(W[r,:] . vin + bias[r]) for both items.
// 128 groups of 8 lanes; group g handles rows g, g+128. Lane l covers
// float4-chunks i == l (mod 8). NCH = (cols/4)/8 chunks per lane.
template<int NCH>
__device__ __forceinline__ void layerT(
    const float* __restrict__ W, const float* __restrict__ bias,
    const float* __restrict__ vinA, const float* __restrict__ vinB,
    float* __restrict__ outA, float* __restrict__ outB,
    int rows, int grp, int l)
{
    const float4* __restrict__ ua = reinterpret_cast<const float4*>(vinA);
    const float4* __restrict__ ub = reinterpret_cast<const float4*>(vinB);
    for (int r = grp; r < rows; r += 128) {
        const float4* __restrict__ w4 =
            reinterpret_cast<const float4*>(W) + r * (NCH * 8);
        float4 p = make_float4(0.f, 0.f, 0.f, 0.f);
        float4 q = make_float4(0.f, 0.f, 0.f, 0.f);
#pragma unroll
        for (int kb = 0; kb < NCH; kb += 4) {
            float4 w[4];
#pragma unroll
            for (int j = 0; j < 4; j++)
                if (kb + j < NCH) w[j] = __ldg(w4 + (kb + j) * 8 + l);
#pragma unroll
            for (int j = 0; j < 4; j++)
                if (kb + j < NCH) {
                    const int i = (kb + j) * 8 + l;
                    float4 u = ua[i];
                    float4 v = ub[i];
                    p.x = fmaf(w[j].x, u.x, p.x);
                    p.y = fmaf(w[j].y, u.y, p.y);
                    p.z = fmaf(w[j].z, u.z, p.z);
                    p.w = fmaf(w[j].w, u.w, p.w);
                    q.x = fmaf(w[j].x, v.x, q.x);
                    q.y = fmaf(w[j].y, v.y, q.y);
                    q.z = fmaf(w[j].z, v.z, q.z);
                    q.w = fmaf(w[j].w, v.w, q.w);
                }
        }
        float rp = (p.x + p.y) + (p.z + p.w);
        float rq = (q.x + q.y) + (q.z + q.w);
#pragma unroll
        for (int o = 1; o < 8; o <<= 1) {
            rp += __shfl_xor_sync(0xffffffffu, rp, o);
            rq += __shfl_xor_sync(0xffffffffu, rq, o);
        }
        if (l == 0) {
            float bs = __ldg(bias + r);
            outA[r] = fmaxf(rp + bs, 0.f);
            outB[r] = fmaxf(rq + bs, 0.f);
        }
    }
}

__global__ __launch_bounds__(1024)
void gat_ldg_kernel(
    const float* __restrict__ x, const int* __restrict__ company_idx,
    const float* __restrict__ W_in,  const float* __restrict__ b_in,
    const float* __restrict__ gat_W, const float* __restrict__ gat_b,
    const float* __restrict__ emb,
    const float* __restrict__ W_fuse, const float* __restrict__ b_fuse,
    const float* __restrict__ W_p1, const float* __restrict__ b_p1,
    const float* __restrict__ W_p2, const float* __restrict__ b_p2,
    const float* __restrict__ W_p3, const float* __restrict__ b_p3,
    const float* __restrict__ W_d1, const float* __restrict__ b_d1,
    const float* __restrict__ W_d2, const float* __restrict__ b_d2,
    const float* __restrict__ W_d3, const float* __restrict__ b_d3,
    float* __restrict__ out)
{
    __shared__ __align__(16) float act[2 * ACT_STRIDE];

    const int tid = threadIdx.x;
    const int b0  = blockIdx.x * 2;
    const int grp = tid >> 3;
    const int l   = tid & 7;

    float* sA0 = act;                    // item0: s0
    float* sB0 = act + ACT_STRIDE;       // item1: s0
    float* sA1 = act + 320;              // item0: s1
    float* sB1 = act + ACT_STRIDE + 320;
    float* sA2 = act + 576;              // item0: s2
    float* sB2 = act + ACT_STRIDE + 576;

    // init: x rows + emb rows for both items
    if (tid < 128) {
        const int it = tid >> 6, c = tid & 63;
        const int bb = b0 + it;
        float* s0 = act + it * ACT_STRIDE;
        s0[c]       = __ldg(&x[bb * IN_DIM + c]);
        s0[256 + c] = __ldg(&emb[__ldg(&company_idx[bb]) * IN_DIM + c]);
    }
    __syncthreads();

    // W_in: 256x64, s0 -> s1
    layerT<2>(W_in, b_in, sA0, sB0, sA1, sB1, 256, grp, l);
    __syncthreads();
    // GAT layers (uniform-node collapse): 256x256
    layerT<8>(gat_W,          gat_b,       sA1, sB1, sA0, sB0, 256, grp, l);
    __syncthreads();
    layerT<8>(gat_W +  65536, gat_b + 256, sA0, sB0, sA1, sB1, 256, grp, l);
    __syncthreads();
    layerT<8>(gat_W + 131072, gat_b + 512, sA1, sB1, sA0, sB0, 256, grp, l);
    __syncthreads();
    // fuse: 256x320 (s0 = [gat2 | emb]) -> s1
    layerT<10>(W_fuse, b_fuse, sA0, sB0, sA1, sB1, 256, grp, l);
    __syncthreads();
    // p1: 128x256 s1 -> s0[0:128]; d1: 128x256 s1 -> s0[128:256]
    layerT<8>(W_p1, b_p1, sA1, sB1, sA0, sB0, 128, grp, l);
    layerT<8>(W_d1, b_d1, sA1, sB1, sA0 + 128, sB0 + 128, 128, grp, l);
    __syncthreads();
    // p2: 64x128 s0[0:128] -> s2[0:64]; d2: 64x128 s0[128:256] -> s2[64:128]
    layerT<4>(W_p2, b_p2, sA0, sB0, sA2, sB2, 64, grp, l);
    layerT<4>(W_d2, b_d2, sA0 + 128, sB0 + 128, sA2 + 64, sB2 + 64, 64, grp, l);
    __syncthreads();

    // heads: warp w -> (item = w>>1, head = w&1)
    const int w = tid >> 5, lane = tid & 31;
    if (w < 4) {
        const int it = w >> 1, head = w & 1;
        const float* s2 = act + it * ACT_STRIDE + 576 + head * 64;
        const float* Wt = head ? W_d3 : W_p3;
        float2 wv = __ldg(&reinterpret_cast<const float2*>(Wt)[lane]);
        float2 vv = reinterpret_cast<const float2*>(s2)[lane];
        float r = fmaf(wv.x, vv.x, wv.y * vv.y);
#pragma unroll
        for (int o = 16; o; o >>= 1) r += __shfl_xor_sync(0xffffffffu, r, o);
        if (lane == 0) {
            const int bb = b0 + it;
            if (head == 0) out[bb] = r + __ldg(b_p3);
            else           out[64 + bb] = 1.f / (1.f + expf(-(r + __ldg(b_d3))));
        }
    }
}

extern "C" void kernel_launch(void* const* d_in, const int* in_sizes, int n_in,
                              void* d_out, int out_size) {
    const float* x      = (const float*)d_in[0];
    const int*   ci     = (const int*)  d_in[1];
    const float* W_in   = (const float*)d_in[4];
    const float* b_in   = (const float*)d_in[5];
    const float* gat_W  = (const float*)d_in[6];
    const float* gat_b  = (const float*)d_in[11];
    const float* emb    = (const float*)d_in[12];
    const float* W_fuse = (const float*)d_in[13];
    const float* b_fuse = (const float*)d_in[14];
    const float* W_p1   = (const float*)d_in[15];
    const float* b_p1   = (const float*)d_in[16];
    const float* W_p2   = (const float*)d_in[17];
    const float* b_p2   = (const float*)d_in[18];
    const float* W_p3   = (const float*)d_in[19];
    const float* b_p3   = (const float*)d_in[20];
    const float* W_d1   = (const float*)d_in[21];
    const float* b_d1   = (const float*)d_in[22];
    const float* W_d2   = (const float*)d_in[23];
    const float* b_d2   = (const float*)d_in[24];
    const float* W_d3   = (const float*)d_in[25];
    const float* b_d3   = (const float*)d_in[26];

    const int B = in_sizes[0] / IN_DIM;  // 64

    gat_ldg_kernel<<<B / 2, 1024>>>(
        x, ci, W_in, b_in, gat_W, gat_b, emb, W_fuse, b_fuse,
        W_p1, b_p1, W_p2, b_p2, W_p3, b_p3,
        W_d1, b_d1, W_d2, b_d2, W_d3, b_d3,
        (float*)d_out);
}

// round 10
// speedup vs baseline: 3.4788x; 1.4467x over previous
#include <cuda_runtime.h>
#include <math.h>
#include <stdint.h>

// EnhancedFinancialGAT collapse: initial node features are uniform over nodes,
// so GAT attention (softmax weights summing to 1 per dst) aggregates identical
// messages -> each GAT layer == relu(W @ g + b). Whole net = per-item MLP.
//
// R9 -> R10: per-SM weight bytes are the floor (1.45MB @ ~128B/cyc). Split
// each layer's rows across a 2-CTA cluster: each CTA streams 0.72MB, halves
// exchanged via st.shared::cluster + barrier.cluster (5 syncs). After fuse,
// rank0 runs the price branch, rank1 the direction branch (no more syncs).

#define IN_DIM 64
#define ACT_STRIDE 704   // per item: s0[320] | s1[256] | s2[128]

__device__ __forceinline__ uint32_t smem_u32(const void* p) {
    uint32_t a;
    asm("{ .reg .u64 t; cvta.to.shared.u64 t, %1; cvt.u32.u64 %0, t; }"
        : "=r"(a) : "l"(p));
    return a;
}
__device__ __forceinline__ uint32_t mapa_u32(uint32_t addr, uint32_t rank) {
    uint32_t r;
    asm("mapa.shared::cluster.u32 %0, %1, %2;" : "=r"(r) : "r"(addr), "r"(rank));
    return r;
}
__device__ __forceinline__ void st_peer(uint32_t addr, float v) {
    asm volatile("st.shared::cluster.f32 [%0], %1;" :: "r"(addr), "f"(v) : "memory");
}
__device__ __forceinline__ void cluster_sync() {
    asm volatile("barrier.cluster.arrive.aligned;" ::: "memory");
    asm volatile("barrier.cluster.wait.aligned;" ::: "memory");
}

// One output row of a dense layer for both items. Group of 8 lanes covers the
// row; lane l reads float4-chunks (kb*8 + l) -> 128B-coalesced warp LDGs.
template<int NCH>
__device__ __forceinline__ void dense_row(
    const float* __restrict__ W, const float* __restrict__ bias,
    const float* __restrict__ vA, const float* __restrict__ vB,
    float* __restrict__ act, uint32_t peer_u, bool bcast,
    int out_off, int row, int l)
{
    const float4* __restrict__ w4 = reinterpret_cast<const float4*>(W) + row * (NCH * 8);
    const float4* __restrict__ ua = reinterpret_cast<const float4*>(vA);
    const float4* __restrict__ ub = reinterpret_cast<const float4*>(vB);
    float4 p = make_float4(0.f, 0.f, 0.f, 0.f);
    float4 q = make_float4(0.f, 0.f, 0.f, 0.f);
#pragma unroll
    for (int kb = 0; kb < NCH; kb += 4) {
        float4 w[4];
#pragma unroll
        for (int j = 0; j < 4; j++)
            if (kb + j < NCH) w[j] = __ldg(w4 + (kb + j) * 8 + l);
#pragma unroll
        for (int j = 0; j < 4; j++)
            if (kb + j < NCH) {
                const int i = (kb + j) * 8 + l;
                float4 u = ua[i];
                float4 v = ub[i];
                p.x = fmaf(w[j].x, u.x, p.x);
                p.y = fmaf(w[j].y, u.y, p.y);
                p.z = fmaf(w[j].z, u.z, p.z);
                p.w = fmaf(w[j].w, u.w, p.w);
                q.x = fmaf(w[j].x, v.x, q.x);
                q.y = fmaf(w[j].y, v.y, q.y);
                q.z = fmaf(w[j].z, v.z, q.z);
                q.w = fmaf(w[j].w, v.w, q.w);
            }
    }
    float rp = (p.x + p.y) + (p.z + p.w);
    float rq = (q.x + q.y) + (q.z + q.w);
#pragma unroll
    for (int o = 1; o < 8; o <<= 1) {
        rp += __shfl_xor_sync(0xffffffffu, rp, o);
        rq += __shfl_xor_sync(0xffffffffu, rq, o);
    }
    if (l == 0) {
        const float bs = __ldg(bias + row);
        const float a = fmaxf(rp + bs, 0.f);
        const float b = fmaxf(rq + bs, 0.f);
        act[out_off + row] = a;
        act[ACT_STRIDE + out_off + row] = b;
        if (bcast) {
            st_peer(peer_u + (out_off + row) * 4, a);
            st_peer(peer_u + (ACT_STRIDE + out_off + row) * 4, b);
        }
    }
}

__global__ __launch_bounds__(1024) __cluster_dims__(2, 1, 1)
void gat_cluster_kernel(
    const float* __restrict__ x, const int* __restrict__ company_idx,
    const float* __restrict__ W_in,  const float* __restrict__ b_in,
    const float* __restrict__ gat_W, const float* __restrict__ gat_b,
    const float* __restrict__ emb,
    const float* __restrict__ W_fuse, const float* __restrict__ b_fuse,
    const float* __restrict__ W_p1, const float* __restrict__ b_p1,
    const float* __restrict__ W_p2, const float* __restrict__ b_p2,
    const float* __restrict__ W_p3, const float* __restrict__ b_p3,
    const float* __restrict__ W_d1, const float* __restrict__ b_d1,
    const float* __restrict__ W_d2, const float* __restrict__ b_d2,
    const float* __restrict__ W_d3, const float* __restrict__ b_d3,
    float* __restrict__ out)
{
    __shared__ __align__(16) float act[2 * ACT_STRIDE];

    const int tid  = threadIdx.x;
    const int grp  = tid >> 3;          // 0..127
    const int l    = tid & 7;
    uint32_t rank;
    asm("mov.u32 %0, %%cluster_ctarank;" : "=r"(rank));
    const int b0   = (blockIdx.x >> 1) * 2;   // 2 items per cluster
    const int base = rank * 128;              // row half owned by this CTA

    const uint32_t peer_u = mapa_u32(smem_u32(act), rank ^ 1);

    float* A = act;                 // item0 base
    float* Bk = act + ACT_STRIDE;   // item1 base

    // init: x rows + emb rows for both items (each CTA loads its own copy)
    if (tid < 128) {
        const int it = tid >> 6, c = tid & 63;
        const int bb = b0 + it;
        float* s0 = act + it * ACT_STRIDE;
        s0[c]       = __ldg(&x[bb * IN_DIM + c]);
        s0[256 + c] = __ldg(&emb[__ldg(&company_idx[bb]) * IN_DIM + c]);
    }
    __syncthreads();

    // W_in: 256x64, s0[0:64] -> s1 (rows split by rank)
    dense_row<2>(W_in, b_in, A, Bk, act, peer_u, true, 320, base + grp, l);
    cluster_sync();
    // GAT layers (uniform-node collapse): 256x256
    dense_row<8>(gat_W,          gat_b,       A + 320, Bk + 320, act, peer_u, true, 0,   base + grp, l);
    cluster_sync();
    dense_row<8>(gat_W +  65536, gat_b + 256, A,       Bk,       act, peer_u, true, 320, base + grp, l);
    cluster_sync();
    dense_row<8>(gat_W + 131072, gat_b + 512, A + 320, Bk + 320, act, peer_u, true, 0,   base + grp, l);
    cluster_sync();
    // fuse: 256x320  (s0 = [gat2 out | emb]) -> s1
    dense_row<10>(W_fuse, b_fuse, A, Bk, act, peer_u, true, 320, base + grp, l);
    cluster_sync();

    // branch: rank0 = price path, rank1 = direction path (fully local)
    const float* W1 = rank ? W_d1 : W_p1;
    const float* c1 = rank ? b_d1 : b_p1;
    const float* W2 = rank ? W_d2 : W_p2;
    const float* c2 = rank ? b_d2 : b_p2;
    const float* W3 = rank ? W_d3 : W_p3;
    const float* c3 = rank ? b_d3 : b_p3;

    // l1: 128x256, s1 -> s0[0:128]
    dense_row<8>(W1, c1, A + 320, Bk + 320, act, peer_u, false, 0, grp, l);
    __syncthreads();
    // l2: 64x128, s0[0:128] -> s2[576:640]
    if (grp < 64)
        dense_row<4>(W2, c2, A, Bk, act, peer_u, false, 576, grp, l);
    __syncthreads();

    // head: warp 0 -> item0, warp 1 -> item1
    const int w = tid >> 5, lane = tid & 31;
    if (w < 2) {
        const float* s2 = act + w * ACT_STRIDE + 576;
        float2 wv = __ldg(&reinterpret_cast<const float2*>(W3)[lane]);
        float2 vv = reinterpret_cast<const float2*>(s2)[lane];
        float r = fmaf(wv.x, vv.x, wv.y * vv.y);
#pragma unroll
        for (int o = 16; o; o >>= 1) r += __shfl_xor_sync(0xffffffffu, r, o);
        if (lane == 0) {
            const int bb = b0 + w;
            const float v = r + __ldg(c3);
            if (rank == 0) out[bb] = v;                              // price
            else           out[64 + bb] = 1.f / (1.f + expf(-v));    // direction
        }
    }
}

extern "C" void kernel_launch(void* const* d_in, const int* in_sizes, int n_in,
                              void* d_out, int out_size) {
    const float* x      = (const float*)d_in[0];
    const int*   ci     = (const int*)  d_in[1];
    const float* W_in   = (const float*)d_in[4];
    const float* b_in   = (const float*)d_in[5];
    const float* gat_W  = (const float*)d_in[6];
    const float* gat_b  = (const float*)d_in[11];
    const float* emb    = (const float*)d_in[12];
    const float* W_fuse = (const float*)d_in[13];
    const float* b_fuse = (const float*)d_in[14];
    const float* W_p1   = (const float*)d_in[15];
    const float* b_p1   = (const float*)d_in[16];
    const float* W_p2   = (const float*)d_in[17];
    const float* b_p2   = (const float*)d_in[18];
    const float* W_p3   = (const float*)d_in[19];
    const float* b_p3   = (const float*)d_in[20];
    const float* W_d1   = (const float*)d_in[21];
    const float* b_d1   = (const float*)d_in[22];
    const float* W_d2   = (const float*)d_in[23];
    const float* b_d2   = (const float*)d_in[24];
    const float* W_d3   = (const float*)d_in[25];
    const float* b_d3   = (const float*)d_in[26];

    const int B = in_sizes[0] / IN_DIM;  // 64

    // 2 CTAs per cluster, 2 items per cluster -> B/2 * 2 / 2 = B blocks... :
    // clusters = B/2, CTAs = B. (cluster dims baked into the kernel attr)
    gat_cluster_kernel<<<B, 1024>>>(
        x, ci, W_in, b_in, gat_W, gat_b, emb, W_fuse, b_fuse,
        W_p1, b_p1, W_p2, b_p2, W_p3, b_p3,
        W_d1, b_d1, W_d2, b_d2, W_d3, b_d3,
        (float*)d_out);
}

// round 11
// speedup vs baseline: 3.8430x; 1.1047x over previous
#include <cuda_runtime.h>
#include <math.h>
#include <stdint.h>

// EnhancedFinancialGAT collapse: initial node features are uniform over nodes,
// so GAT attention (softmax weights summing to 1 per dst) aggregates identical
// messages -> each GAT layer == relu(W @ g + b). Whole net = per-item MLP.
//
// R10 -> R11: cluster-4 row split (64 rows/CTA, 0.36MB/CTA), 16 lanes per row
// -> single 4-deep LDG batch per shared stage (one load-wave). grid=128 SMs.
// Tail fans out rank=(branch,item) with zero cluster syncs.

#define IN_DIM 64
#define ACT_STRIDE 704   // per item: s0[320] | s1[256] | s2[128]

__device__ __forceinline__ uint32_t smem_u32(const void* p) {
    uint32_t a;
    asm("{ .reg .u64 t; cvta.to.shared.u64 t, %1; cvt.u32.u64 %0, t; }"
        : "=r"(a) : "l"(p));
    return a;
}
__device__ __forceinline__ uint32_t mapa_u32(uint32_t addr, uint32_t rank) {
    uint32_t r;
    asm("mapa.shared::cluster.u32 %0, %1, %2;" : "=r"(r) : "r"(addr), "r"(rank));
    return r;
}
__device__ __forceinline__ void st_peer(uint32_t addr, float v) {
    asm volatile("st.shared::cluster.f32 [%0], %1;" :: "r"(addr), "f"(v) : "memory");
}
__device__ __forceinline__ void cluster_sync() {
    asm volatile("barrier.cluster.arrive.aligned;" ::: "memory");
    asm volatile("barrier.cluster.wait.aligned;" ::: "memory");
}

// Shared layer row (both items), 16 lanes per row. Lane l reads chunk j*16+l
// -> 256B contiguous per row, fully coalesced. Result broadcast to all 4 CTAs.
template<int NCH>
__device__ __forceinline__ void shared_layer16(
    const float* __restrict__ W, const float* __restrict__ bias,
    const float* __restrict__ act, int in_off, int out_off,
    int row, int l, const uint32_t* __restrict__ peer)
{
    const float4* __restrict__ w4 = reinterpret_cast<const float4*>(W) + row * (NCH * 16);
    const float4* __restrict__ ua = reinterpret_cast<const float4*>(act + in_off);
    const float4* __restrict__ ub = reinterpret_cast<const float4*>(act + ACT_STRIDE + in_off);
    float4 w[NCH];
#pragma unroll
    for (int j = 0; j < NCH; j++) w[j] = __ldg(w4 + j * 16 + l);
    float4 p = make_float4(0.f, 0.f, 0.f, 0.f);
    float4 q = make_float4(0.f, 0.f, 0.f, 0.f);
#pragma unroll
    for (int j = 0; j < NCH; j++) {
        const float4 u = ua[j * 16 + l];
        const float4 v = ub[j * 16 + l];
        p.x = fmaf(w[j].x, u.x, p.x); p.y = fmaf(w[j].y, u.y, p.y);
        p.z = fmaf(w[j].z, u.z, p.z); p.w = fmaf(w[j].w, u.w, p.w);
        q.x = fmaf(w[j].x, v.x, q.x); q.y = fmaf(w[j].y, v.y, q.y);
        q.z = fmaf(w[j].z, v.z, q.z); q.w = fmaf(w[j].w, v.w, q.w);
    }
    float rp = (p.x + p.y) + (p.z + p.w);
    float rq = (q.x + q.y) + (q.z + q.w);
#pragma unroll
    for (int o = 1; o < 16; o <<= 1) {
        rp += __shfl_xor_sync(0xffffffffu, rp, o);
        rq += __shfl_xor_sync(0xffffffffu, rq, o);
    }
    if (l == 0) {
        const float bs = __ldg(bias + row);
        const float a  = fmaxf(rp + bs, 0.f);
        const float b2 = fmaxf(rq + bs, 0.f);
#pragma unroll
        for (int r = 0; r < 4; r++) {
            st_peer(peer[r] + (uint32_t)(out_off + row) * 4, a);
            st_peer(peer[r] + (uint32_t)(ACT_STRIDE + out_off + row) * 4, b2);
        }
    }
}

// Local tail layer row (one item), 8 lanes per row.
template<int NCH>
__device__ __forceinline__ void local_layer8(
    const float* __restrict__ W, const float* __restrict__ bias,
    const float* __restrict__ vin, float* __restrict__ vout,
    int row, int l)
{
    const float4* __restrict__ w4 = reinterpret_cast<const float4*>(W) + row * (NCH * 8);
    const float4* __restrict__ u4 = reinterpret_cast<const float4*>(vin);
    float4 w[NCH];
#pragma unroll
    for (int j = 0; j < NCH; j++) w[j] = __ldg(w4 + j * 8 + l);
    float4 p = make_float4(0.f, 0.f, 0.f, 0.f);
#pragma unroll
    for (int j = 0; j < NCH; j++) {
        const float4 u = u4[j * 8 + l];
        p.x = fmaf(w[j].x, u.x, p.x); p.y = fmaf(w[j].y, u.y, p.y);
        p.z = fmaf(w[j].z, u.z, p.z); p.w = fmaf(w[j].w, u.w, p.w);
    }
    float r = (p.x + p.y) + (p.z + p.w);
#pragma unroll
    for (int o = 1; o < 8; o <<= 1) r += __shfl_xor_sync(0xffffffffu, r, o);
    if (l == 0) vout[row] = fmaxf(r + __ldg(bias + row), 0.f);
}

__global__ __launch_bounds__(1024) __cluster_dims__(4, 1, 1)
void gat_c4_kernel(
    const float* __restrict__ x, const int* __restrict__ company_idx,
    const float* __restrict__ W_in,  const float* __restrict__ b_in,
    const float* __restrict__ gat_W, const float* __restrict__ gat_b,
    const float* __restrict__ emb,
    const float* __restrict__ W_fuse, const float* __restrict__ b_fuse,
    const float* __restrict__ W_p1, const float* __restrict__ b_p1,
    const float* __restrict__ W_p2, const float* __restrict__ b_p2,
    const float* __restrict__ W_p3, const float* __restrict__ b_p3,
    const float* __restrict__ W_d1, const float* __restrict__ b_d1,
    const float* __restrict__ W_d2, const float* __restrict__ b_d2,
    const float* __restrict__ W_d3, const float* __restrict__ b_d3,
    float* __restrict__ out)
{
    __shared__ __align__(16) float act[2 * ACT_STRIDE];

    const int tid   = threadIdx.x;
    const int grp16 = tid >> 4;        // 0..63
    const int l16   = tid & 15;
    const int grp8  = tid >> 3;        // 0..127
    const int l8    = tid & 7;
    uint32_t rank;
    asm("mov.u32 %0, %%cluster_ctarank;" : "=r"(rank));
    const int b0   = (blockIdx.x >> 2) * 2;   // 2 items per 4-CTA cluster
    const int base = rank * 64;               // row quarter owned by this CTA

    uint32_t peer[4];
    {
        const uint32_t a = smem_u32(act);
#pragma unroll
        for (int r = 0; r < 4; r++) peer[r] = mapa_u32(a, r);
    }

    // init: x rows + emb rows for both items (each CTA local copy)
    if (tid < 128) {
        const int it = tid >> 6, c = tid & 63;
        const int bb = b0 + it;
        float* s0 = act + it * ACT_STRIDE;
        s0[c]       = __ldg(&x[bb * IN_DIM + c]);
        s0[256 + c] = __ldg(&emb[__ldg(&company_idx[bb]) * IN_DIM + c]);
    }
    __syncthreads();

    // W_in: 256x64, s0[0:64] -> s1
    shared_layer16<1>(W_in, b_in, act, 0, 320, base + grp16, l16, peer);
    cluster_sync();
    // GAT layers (uniform-node collapse): 256x256
    shared_layer16<4>(gat_W,          gat_b,       act, 320, 0,   base + grp16, l16, peer);
    cluster_sync();
    shared_layer16<4>(gat_W +  65536, gat_b + 256, act, 0,   320, base + grp16, l16, peer);
    cluster_sync();
    shared_layer16<4>(gat_W + 131072, gat_b + 512, act, 320, 0,   base + grp16, l16, peer);
    cluster_sync();
    // fuse: 256x320 (s0 = [gat2 | emb]) -> s1
    shared_layer16<5>(W_fuse, b_fuse, act, 0, 320, base + grp16, l16, peer);
    cluster_sync();

    // tail: rank -> (branch = rank>>1, item = rank&1), fully local
    const int item   = rank & 1;
    const int branch = rank >> 1;            // 0 = price, 1 = direction
    const float* W1 = branch ? W_d1 : W_p1;
    const float* c1 = branch ? b_d1 : b_p1;
    const float* W2 = branch ? W_d2 : W_p2;
    const float* c2 = branch ? b_d2 : b_p2;
    const float* W3 = branch ? W_d3 : W_p3;
    const float* c3 = branch ? b_d3 : b_p3;
    const float* fused = act + item * ACT_STRIDE + 320;

    // l1: 128x256, fused -> act[0:128] (scratch)
    local_layer8<8>(W1, c1, fused, act, grp8, l8);
    __syncthreads();
    // l2: 64x128, act[0:128] -> act[576:640]
    if (grp8 < 64)
        local_layer8<4>(W2, c2, act, act + 576, grp8, l8);
    __syncthreads();

    // head: warp 0, 64-dot
    if (tid < 32) {
        const float2 wv = __ldg(&reinterpret_cast<const float2*>(W3)[tid]);
        const float2 vv = reinterpret_cast<const float2*>(act + 576)[tid];
        float r = fmaf(wv.x, vv.x, wv.y * vv.y);
#pragma unroll
        for (int o = 16; o; o >>= 1) r += __shfl_xor_sync(0xffffffffu, r, o);
        if (tid == 0) {
            const float v = r + __ldg(c3);
            const int bb = b0 + item;
            if (branch == 0) out[bb] = v;                            // price
            else             out[64 + bb] = 1.f / (1.f + expf(-v));  // direction
        }
    }
}

extern "C" void kernel_launch(void* const* d_in, const int* in_sizes, int n_in,
                              void* d_out, int out_size) {
    const float* x      = (const float*)d_in[0];
    const int*   ci     = (const int*)  d_in[1];
    const float* W_in   = (const float*)d_in[4];
    const float* b_in   = (const float*)d_in[5];
    const float* gat_W  = (const float*)d_in[6];
    const float* gat_b  = (const float*)d_in[11];
    const float* emb    = (const float*)d_in[12];
    const float* W_fuse = (const float*)d_in[13];
    const float* b_fuse = (const float*)d_in[14];
    const float* W_p1   = (const float*)d_in[15];
    const float* b_p1   = (const float*)d_in[16];
    const float* W_p2   = (const float*)d_in[17];
    const float* b_p2   = (const float*)d_in[18];
    const float* W_p3   = (const float*)d_in[19];
    const float* b_p3   = (const float*)d_in[20];
    const float* W_d1   = (const float*)d_in[21];
    const float* b_d1   = (const float*)d_in[22];
    const float* W_d2   = (const float*)d_in[23];
    const float* b_d2   = (const float*)d_in[24];
    const float* W_d3   = (const float*)d_in[25];
    const float* b_d3   = (const float*)d_in[26];

    const int B = in_sizes[0] / IN_DIM;  // 64

    // 32 clusters x 4 CTAs = 128 blocks, 2 items per cluster
    gat_c4_kernel<<<B * 2, 1024>>>(
        x, ci, W_in, b_in, gat_W, gat_b, emb, W_fuse, b_fuse,
        W_p1, b_p1, W_p2, b_p2, W_p3, b_p3,
        W_d1, b_d1, W_d2, b_d2, W_d3, b_d3,
        (float*)d_out);
}